// round 15
// baseline (speedup 1.0000x reference)
#include <cuda_runtime.h>

// Problem constants (fixed by the dataset)
#define B_   128
#define E_   100000
#define F_   5000
#define C_   8
#define DIN_ 10
#define DOUT_ 10
#define H_   (F_ * C_)
#define EPS_ 1e-5f

// Transposed scratch (static device mem). Together 102.4 MB -> fits 126 MB L2.
__device__ float g_xT[(size_t)E_ * B_];    // xT[e][b]
__device__ float g_outT[(size_t)E_ * B_];  // outT[e][b] = x + b3, scatter target

// PDL primitives (sm_90+)
__device__ __forceinline__ void pdl_trigger() {
    asm volatile("griddepcontrol.launch_dependents;");
}
__device__ __forceinline__ void pdl_wait() {
    asm volatile("griddepcontrol.wait;" ::: "memory");
}

// ---------------------------------------------------------------------------
// Kernel A (R11 tiling): 32e x 128b per block, MLP=4 loads / 8 stores.
// ---------------------------------------------------------------------------
__global__ __launch_bounds__(256)
void transpose_init_kernel(const float* __restrict__ x,
                           const float* __restrict__ b3) {
    __shared__ float tile[32][129];           // tile[e_loc][b]
    pdl_trigger();

    const int e0 = blockIdx.x * 32;
    const int tx = threadIdx.x;               // 0..7
    const int ty = threadIdx.y;               // 0..31

#pragma unroll
    for (int j = 0; j < 4; j++) {
        const int b = ty + 32 * j;
        float4 v = __ldcs(reinterpret_cast<const float4*>(
                              x + (size_t)b * E_ + e0) + tx);
        tile[tx * 4 + 0][b] = v.x;
        tile[tx * 4 + 1][b] = v.y;
        tile[tx * 4 + 2][b] = v.z;
        tile[tx * 4 + 3][b] = v.w;
    }
    __syncthreads();
    {
        const int e = e0 + ty;
        const float bias = __ldg(b3 + e);
        const size_t row = (size_t)e * B_;
#pragma unroll
        for (int j = 0; j < 4; j++) {
            const int bb = 4 * (tx + 8 * j);
            float4 w;
            w.x = tile[ty][bb + 0];
            w.y = tile[ty][bb + 1];
            w.z = tile[ty][bb + 2];
            w.w = tile[ty][bb + 3];
            *reinterpret_cast<float4*>(&g_xT[row + bb]) = w;
            float4 w2;
            w2.x = w.x + bias; w2.y = w.y + bias;
            w2.z = w.z + bias; w2.w = w.w + bias;
            *reinterpret_cast<float4*>(&g_outT[row + bb]) = w2;
        }
    }
}

// ---------------------------------------------------------------------------
// Kernel D (R11 tiling): outT[e][b] -> out[b][e]. PDL-waits before reading.
// ---------------------------------------------------------------------------
__global__ __launch_bounds__(256)
void transpose_out_kernel(float* __restrict__ out) {
    __shared__ float tile[32][129];           // tile[e_loc][b]
    const int e0 = blockIdx.x * 32;
    const int tx = threadIdx.x;
    const int ty = threadIdx.y;

    pdl_wait();      // fn's atomics must be visible

    {
        const int e = e0 + ty;
        const size_t row = (size_t)e * B_;
#pragma unroll
        for (int j = 0; j < 4; j++) {
            const int bb = 4 * (tx + 8 * j);
            float4 v = __ldcs(reinterpret_cast<const float4*>(&g_outT[row + bb]));
            tile[ty][bb + 0] = v.x;
            tile[ty][bb + 1] = v.y;
            tile[ty][bb + 2] = v.z;
            tile[ty][bb + 3] = v.w;
        }
    }
    __syncthreads();
#pragma unroll
    for (int j = 0; j < 4; j++) {
        const int b = ty + 32 * j;
        float4 w;
        w.x = tile[tx * 4 + 0][b];
        w.y = tile[tx * 4 + 1][b];
        w.z = tile[tx * 4 + 2][b];
        w.w = tile[tx * 4 + 3][b];
        __stcs(reinterpret_cast<float4*>(out + (size_t)b * E_ + e0) + tx, w);
    }
}

// Fast ELU: MUFU.EX2-based.
__device__ __forceinline__ float elu1(float z) {
    return z > 0.0f ? z : __expf(z) - 1.0f;
}

// Vectorized global reduce-add, 16B per lane (sm_90+).
__device__ __forceinline__ void red_add_v4(float* addr, float a, float b,
                                           float c, float d) {
    asm volatile("red.global.add.v4.f32 [%0], {%1, %2, %3, %4};"
                 :: "l"(addr), "f"(a), "f"(b), "f"(c), "f"(d)
                 : "memory");
}

// ---------------------------------------------------------------------------
// Kernel C: one block per f, one thread per batch b.
// Changes this round: __ldcs gathers (xT single-use -> keep outT in L2);
// mild occupancy bump (min 11 CTAs/SM, reg cap ~46).
// ---------------------------------------------------------------------------
__global__ __launch_bounds__(B_, 11)
void fn_node_kernel(const float* __restrict__ s,
                    const float* __restrict__ w1,
                    const float* __restrict__ b1,
                    const float* __restrict__ w2,
                    const float* __restrict__ b2,
                    const float* __restrict__ w3,
                    const int*   __restrict__ src1,   // in_e[f,d] = src1[(f*10+d)*8]
                    const int*   __restrict__ dst3,   // out_e[f,d] = dst3[(f*10+d)*8]
                    const float* __restrict__ g1,
                    const float* __restrict__ bt1,
                    const float* __restrict__ g2,
                    const float* __restrict__ bt2) {
    __shared__ float w1s[DIN_ * C_];
    __shared__ float w2s[C_ * C_];
    __shared__ float w3s[DOUT_ * C_];
    __shared__ int   ine[DIN_];
    __shared__ int   oute[DOUT_];
    __shared__ float b1s[C_], b2s[C_], g1s[C_], bt1s[C_], g2s[C_], bt2s[C_];
    __shared__ __align__(16) float sc[DOUT_][B_];   // scatter staging (5 KB)

    const int f   = blockIdx.x;
    const int tid = threadIdx.x;   // == batch index b
    const int b   = tid;

    // ---- independent preamble: s loads (streaming) + param staging ----
    const float4* srow = reinterpret_cast<const float4*>(s + (size_t)b * H_ + f * C_);
    float4 sa = __ldcs(srow);
    float4 sb = __ldcs(srow + 1);

    if (tid < DIN_ * C_)  w1s[tid] = w1[f * (DIN_ * C_) + tid];
    if (tid < C_ * C_)    w2s[tid] = w2[f * (C_ * C_) + tid];
    if (tid < DOUT_ * C_) w3s[tid] = w3[f * (DOUT_ * C_) + tid];
    if (tid < DIN_)       ine[tid]  = src1[(f * DIN_ + tid) * C_];
    if (tid < DOUT_)      oute[tid] = dst3[(f * DOUT_ + tid) * C_];
    if (tid < C_) {
        int hc = f * C_ + tid;
        b1s[tid]  = b1[hc];
        b2s[tid]  = b2[hc];
        g1s[tid]  = g1[hc];
        bt1s[tid] = bt1[hc];
        g2s[tid]  = g2[hc];
        bt2s[tid] = bt2[hc];
    }
    __syncthreads();

    // ---- gate on init's xT/outT stores being visible ----
    pdl_wait();

    // ---- gather from transposed x: coalesced, MLP=10, evict-first ----
    float xv[DIN_];
#pragma unroll
    for (int d = 0; d < DIN_; d++) xv[d] = __ldcs(&g_xT[(size_t)ine[d] * B_ + b]);

    float sv[C_] = {sa.x, sa.y, sa.z, sa.w, sb.x, sb.y, sb.z, sb.w};

    // ---- w1: 10x8 dense ----
    float h[C_];
#pragma unroll
    for (int c = 0; c < C_; c++) {
        float acc = b1s[c];
#pragma unroll
        for (int d = 0; d < DIN_; d++) acc = fmaf(xv[d], w1s[d * C_ + c], acc);
        h[c] = acc;
    }

    // ---- groupLN 1 + affine + elu(s*h) ----
    {
        float sum = 0.f, sq = 0.f;
#pragma unroll
        for (int c = 0; c < C_; c++) { sum += h[c]; sq += h[c] * h[c]; }
        float mu  = sum * 0.125f;
        float var = sq * 0.125f - mu * mu;
        float inv = rsqrtf(var + EPS_);
#pragma unroll
        for (int c = 0; c < C_; c++) {
            float z = (g1s[c] * ((h[c] - mu) * inv) + bt1s[c]) * sv[c];
            h[c] = elu1(z);
        }
    }

    // ---- w2: 8x8 dense block ----
    float h2[C_];
#pragma unroll
    for (int c2 = 0; c2 < C_; c2++) {
        float acc = b2s[c2];
#pragma unroll
        for (int c = 0; c < C_; c++) acc = fmaf(h[c], w2s[c * C_ + c2], acc);
        h2[c2] = acc;
    }

    // ---- groupLN 2 + affine + elu(h*s) ----
    {
        float sum = 0.f, sq = 0.f;
#pragma unroll
        for (int c = 0; c < C_; c++) { sum += h2[c]; sq += h2[c] * h2[c]; }
        float mu  = sum * 0.125f;
        float var = sq * 0.125f - mu * mu;
        float inv = rsqrtf(var + EPS_);
#pragma unroll
        for (int c = 0; c < C_; c++) {
            float z = (g2s[c] * ((h2[c] - mu) * inv) + bt2s[c]) * sv[c];
            h[c] = elu1(z);
        }
    }

    // ---- w3: 8 -> 10, stage per-edge contributions in smem ----
#pragma unroll
    for (int d = 0; d < DOUT_; d++) {
        float acc = 0.f;
#pragma unroll
        for (int c = 0; c < C_; c++) acc = fmaf(h[c], w3s[d * C_ + c], acc);
        sc[d][b] = acc;
    }
    __syncthreads();

    pdl_trigger();   // staging done -> let transpose_out ramp during scatter

    // ---- vectorized scatter: 10 edges x 32 red.v4 lanes ----
#pragma unroll
    for (int i = tid; i < DOUT_ * 32; i += B_) {
        int d = i >> 5;
        int l = i & 31;
        const float* v = &sc[d][l * 4];
        red_add_v4(&g_outT[(size_t)oute[d] * B_ + l * 4], v[0], v[1], v[2], v[3]);
    }
}

// ---------------------------------------------------------------------------
// Launch (PDL on the two dependent kernels)
// ---------------------------------------------------------------------------
extern "C" void kernel_launch(void* const* d_in, const int* in_sizes, int n_in,
                              void* d_out, int out_size) {
    const float* x   = (const float*)d_in[0];
    const float* s   = (const float*)d_in[1];
    const float* w1  = (const float*)d_in[2];
    const float* b1  = (const float*)d_in[3];
    const float* w2  = (const float*)d_in[4];
    const float* b2  = (const float*)d_in[5];
    const float* w3  = (const float*)d_in[6];
    const float* b3  = (const float*)d_in[7];
    const float* g1  = (const float*)d_in[8];
    const float* bt1 = (const float*)d_in[9];
    const float* g2  = (const float*)d_in[10];
    const float* bt2 = (const float*)d_in[11];
    const int*   src1 = (const int*)d_in[12];
    const int*   dst3 = (const int*)d_in[17];
    float* out = (float*)d_out;

    dim3 tblk(8, 32);
    dim3 tgrid(E_ / 32, 1);

    // Kernel A: normal launch.
    transpose_init_kernel<<<tgrid, tblk>>>(x, b3);

    // Kernel C: PDL-dependent on A.
    {
        cudaLaunchConfig_t cfg = {};
        cfg.gridDim  = dim3(F_, 1, 1);
        cfg.blockDim = dim3(B_, 1, 1);
        cudaLaunchAttribute attr[1];
        attr[0].id = cudaLaunchAttributeProgrammaticStreamSerialization;
        attr[0].val.programmaticStreamSerializationAllowed = 1;
        cfg.attrs = attr;
        cfg.numAttrs = 1;
        cudaLaunchKernelEx(&cfg, fn_node_kernel,
                           s, w1, b1, w2, b2, w3, src1, dst3, g1, bt1, g2, bt2);
    }

    // Kernel D: PDL-dependent on C.
    {
        cudaLaunchConfig_t cfg = {};
        cfg.gridDim  = tgrid;
        cfg.blockDim = tblk;
        cudaLaunchAttribute attr[1];
        attr[0].id = cudaLaunchAttributeProgrammaticStreamSerialization;
        attr[0].val.programmaticStreamSerializationAllowed = 1;
        cfg.attrs = attr;
        cfg.numAttrs = 1;
        cudaLaunchKernelEx(&cfg, transpose_out_kernel, out);
    }
}

// round 16
// speedup vs baseline: 1.0732x; 1.0732x over previous
#include <cuda_runtime.h>

// Problem constants (fixed by the dataset)
#define B_   128
#define E_   100000
#define F_   5000
#define C_   8
#define DIN_ 10
#define DOUT_ 10
#define H_   (F_ * C_)
#define EPS_ 1e-5f

// Transposed scratch (static device mem).
__device__ float g_xT[(size_t)E_ * B_];    // xT[e][b] (only rows used by gathers are written)
__device__ float g_outT[(size_t)E_ * B_];  // outT[e][b] = x + b3, scatter target
__device__ unsigned char g_used[E_];       // per-edge gather flag (reset each launch)

// PDL primitives (sm_90+)
__device__ __forceinline__ void pdl_trigger() {
    asm volatile("griddepcontrol.launch_dependents;");
}
__device__ __forceinline__ void pdl_wait() {
    asm volatile("griddepcontrol.wait;" ::: "memory");
}

// ---------------------------------------------------------------------------
// Kernel M: mark edges that appear as gather sources (50k flags).
// ---------------------------------------------------------------------------
__global__ __launch_bounds__(256)
void mark_used_kernel(const int* __restrict__ src1) {
    int i = blockIdx.x * blockDim.x + threadIdx.x;
    if (i < F_ * DIN_) g_used[src1[i * C_]] = 1;
}

// ---------------------------------------------------------------------------
// Kernel A: 32e x 128b tiled transpose; xT stores predicated on g_used
// (61% of rows skipped on average), outT always written.
// ---------------------------------------------------------------------------
__global__ __launch_bounds__(256)
void transpose_init_kernel(const float* __restrict__ x,
                           const float* __restrict__ b3) {
    __shared__ float tile[32][129];           // tile[e_loc][b]
    pdl_trigger();

    const int e0 = blockIdx.x * 32;
    const int tx = threadIdx.x;               // 0..7
    const int ty = threadIdx.y;               // 0..31

#pragma unroll
    for (int j = 0; j < 4; j++) {
        const int b = ty + 32 * j;
        float4 v = __ldcs(reinterpret_cast<const float4*>(
                              x + (size_t)b * E_ + e0) + tx);
        tile[tx * 4 + 0][b] = v.x;
        tile[tx * 4 + 1][b] = v.y;
        tile[tx * 4 + 2][b] = v.z;
        tile[tx * 4 + 3][b] = v.w;
    }
    __syncthreads();
    {
        const int e = e0 + ty;
        const bool used = (g_used[e] != 0);
        const float bias = __ldg(b3 + e);
        const size_t row = (size_t)e * B_;
#pragma unroll
        for (int j = 0; j < 4; j++) {
            const int bb = 4 * (tx + 8 * j);
            float4 w;
            w.x = tile[ty][bb + 0];
            w.y = tile[ty][bb + 1];
            w.z = tile[ty][bb + 2];
            w.w = tile[ty][bb + 3];
            if (used) *reinterpret_cast<float4*>(&g_xT[row + bb]) = w;
            float4 w2;
            w2.x = w.x + bias; w2.y = w.y + bias;
            w2.z = w.z + bias; w2.w = w.w + bias;
            *reinterpret_cast<float4*>(&g_outT[row + bb]) = w2;
        }
    }
}

// ---------------------------------------------------------------------------
// Kernel D: outT[e][b] -> out[b][e]. PDL-waits before reading.
// ---------------------------------------------------------------------------
__global__ __launch_bounds__(256)
void transpose_out_kernel(float* __restrict__ out) {
    __shared__ float tile[32][129];           // tile[e_loc][b]
    const int e0 = blockIdx.x * 32;
    const int tx = threadIdx.x;
    const int ty = threadIdx.y;

    pdl_wait();      // fn's atomics must be visible

    {
        const int e = e0 + ty;
        const size_t row = (size_t)e * B_;
#pragma unroll
        for (int j = 0; j < 4; j++) {
            const int bb = 4 * (tx + 8 * j);
            float4 v = __ldcs(reinterpret_cast<const float4*>(&g_outT[row + bb]));
            tile[ty][bb + 0] = v.x;
            tile[ty][bb + 1] = v.y;
            tile[ty][bb + 2] = v.z;
            tile[ty][bb + 3] = v.w;
        }
    }
    __syncthreads();
#pragma unroll
    for (int j = 0; j < 4; j++) {
        const int b = ty + 32 * j;
        float4 w;
        w.x = tile[tx * 4 + 0][b];
        w.y = tile[tx * 4 + 1][b];
        w.z = tile[tx * 4 + 2][b];
        w.w = tile[tx * 4 + 3][b];
        __stcs(reinterpret_cast<float4*>(out + (size_t)b * E_ + e0) + tx, w);
    }
}

// Fast ELU: MUFU.EX2-based.
__device__ __forceinline__ float elu1(float z) {
    return z > 0.0f ? z : __expf(z) - 1.0f;
}

// Vectorized global reduce-add, 16B per lane (sm_90+).
__device__ __forceinline__ void red_add_v4(float* addr, float a, float b,
                                           float c, float d) {
    asm volatile("red.global.add.v4.f32 [%0], {%1, %2, %3, %4};"
                 :: "l"(addr), "f"(a), "f"(b), "f"(c), "f"(d)
                 : "memory");
}

// ---------------------------------------------------------------------------
// Kernel C (R13/R14 proven config): one block per f, one thread per batch b.
// ---------------------------------------------------------------------------
__global__ __launch_bounds__(B_)
void fn_node_kernel(const float* __restrict__ s,
                    const float* __restrict__ w1,
                    const float* __restrict__ b1,
                    const float* __restrict__ w2,
                    const float* __restrict__ b2,
                    const float* __restrict__ w3,
                    const int*   __restrict__ src1,   // in_e[f,d] = src1[(f*10+d)*8]
                    const int*   __restrict__ dst3,   // out_e[f,d] = dst3[(f*10+d)*8]
                    const float* __restrict__ g1,
                    const float* __restrict__ bt1,
                    const float* __restrict__ g2,
                    const float* __restrict__ bt2) {
    __shared__ float w1s[DIN_ * C_];
    __shared__ float w2s[C_ * C_];
    __shared__ float w3s[DOUT_ * C_];
    __shared__ int   ine[DIN_];
    __shared__ int   oute[DOUT_];
    __shared__ float b1s[C_], b2s[C_], g1s[C_], bt1s[C_], g2s[C_], bt2s[C_];
    __shared__ __align__(16) float sc[DOUT_][B_];   // scatter staging (5 KB)

    const int f   = blockIdx.x;
    const int tid = threadIdx.x;   // == batch index b
    const int b   = tid;

    // ---- independent preamble: s loads (streaming) + param staging ----
    const float4* srow = reinterpret_cast<const float4*>(s + (size_t)b * H_ + f * C_);
    float4 sa = __ldcs(srow);
    float4 sb = __ldcs(srow + 1);

    if (tid < DIN_ * C_)  w1s[tid] = w1[f * (DIN_ * C_) + tid];
    if (tid < C_ * C_)    w2s[tid] = w2[f * (C_ * C_) + tid];
    if (tid < DOUT_ * C_) w3s[tid] = w3[f * (DOUT_ * C_) + tid];
    if (tid < DIN_)       ine[tid]  = src1[(f * DIN_ + tid) * C_];
    if (tid < DOUT_)      oute[tid] = dst3[(f * DOUT_ + tid) * C_];
    if (tid < C_) {
        int hc = f * C_ + tid;
        b1s[tid]  = b1[hc];
        b2s[tid]  = b2[hc];
        g1s[tid]  = g1[hc];
        bt1s[tid] = bt1[hc];
        g2s[tid]  = g2[hc];
        bt2s[tid] = bt2[hc];
    }
    __syncthreads();

    // ---- gate on init's xT/outT stores being visible ----
    pdl_wait();

    // ---- gather from transposed x: fully coalesced, MLP=10 ----
    float xv[DIN_];
#pragma unroll
    for (int d = 0; d < DIN_; d++) xv[d] = __ldg(&g_xT[(size_t)ine[d] * B_ + b]);

    float sv[C_] = {sa.x, sa.y, sa.z, sa.w, sb.x, sb.y, sb.z, sb.w};

    // ---- w1: 10x8 dense ----
    float h[C_];
#pragma unroll
    for (int c = 0; c < C_; c++) {
        float acc = b1s[c];
#pragma unroll
        for (int d = 0; d < DIN_; d++) acc = fmaf(xv[d], w1s[d * C_ + c], acc);
        h[c] = acc;
    }

    // ---- groupLN 1 + affine + elu(s*h) ----
    {
        float sum = 0.f, sq = 0.f;
#pragma unroll
        for (int c = 0; c < C_; c++) { sum += h[c]; sq += h[c] * h[c]; }
        float mu  = sum * 0.125f;
        float var = sq * 0.125f - mu * mu;
        float inv = rsqrtf(var + EPS_);
#pragma unroll
        for (int c = 0; c < C_; c++) {
            float z = (g1s[c] * ((h[c] - mu) * inv) + bt1s[c]) * sv[c];
            h[c] = elu1(z);
        }
    }

    // ---- w2: 8x8 dense block ----
    float h2[C_];
#pragma unroll
    for (int c2 = 0; c2 < C_; c2++) {
        float acc = b2s[c2];
#pragma unroll
        for (int c = 0; c < C_; c++) acc = fmaf(h[c], w2s[c * C_ + c2], acc);
        h2[c2] = acc;
    }

    // ---- groupLN 2 + affine + elu(h*s) ----
    {
        float sum = 0.f, sq = 0.f;
#pragma unroll
        for (int c = 0; c < C_; c++) { sum += h2[c]; sq += h2[c] * h2[c]; }
        float mu  = sum * 0.125f;
        float var = sq * 0.125f - mu * mu;
        float inv = rsqrtf(var + EPS_);
#pragma unroll
        for (int c = 0; c < C_; c++) {
            float z = (g2s[c] * ((h2[c] - mu) * inv) + bt2s[c]) * sv[c];
            h[c] = elu1(z);
        }
    }

    // ---- w3: 8 -> 10, stage per-edge contributions in smem ----
#pragma unroll
    for (int d = 0; d < DOUT_; d++) {
        float acc = 0.f;
#pragma unroll
        for (int c = 0; c < C_; c++) acc = fmaf(h[c], w3s[d * C_ + c], acc);
        sc[d][b] = acc;
    }
    __syncthreads();

    pdl_trigger();   // staging done -> let transpose_out ramp during scatter

    // ---- vectorized scatter: 10 edges x 32 red.v4 lanes ----
#pragma unroll
    for (int i = tid; i < DOUT_ * 32; i += B_) {
        int d = i >> 5;
        int l = i & 31;
        const float* v = &sc[d][l * 4];
        red_add_v4(&g_outT[(size_t)oute[d] * B_ + l * 4], v[0], v[1], v[2], v[3]);
    }
}

// ---------------------------------------------------------------------------
// Launch
// ---------------------------------------------------------------------------
extern "C" void kernel_launch(void* const* d_in, const int* in_sizes, int n_in,
                              void* d_out, int out_size) {
    const float* x   = (const float*)d_in[0];
    const float* s   = (const float*)d_in[1];
    const float* w1  = (const float*)d_in[2];
    const float* b1  = (const float*)d_in[3];
    const float* w2  = (const float*)d_in[4];
    const float* b2  = (const float*)d_in[5];
    const float* w3  = (const float*)d_in[6];
    const float* b3  = (const float*)d_in[7];
    const float* g1  = (const float*)d_in[8];
    const float* bt1 = (const float*)d_in[9];
    const float* g2  = (const float*)d_in[10];
    const float* bt2 = (const float*)d_in[11];
    const int*   src1 = (const int*)d_in[12];
    const int*   dst3 = (const int*)d_in[17];
    float* out = (float*)d_out;

    // Prep: clear + mark used-edge flags (tiny, stream-ordered, capture-safe).
    {
        void* usedPtr = nullptr;
        cudaGetSymbolAddress(&usedPtr, g_used);
        cudaMemsetAsync(usedPtr, 0, E_);
        mark_used_kernel<<<(F_ * DIN_ + 255) / 256, 256>>>(src1);
    }

    dim3 tblk(8, 32);
    dim3 tgrid(E_ / 32, 1);

    // Kernel A: normal launch.
    transpose_init_kernel<<<tgrid, tblk>>>(x, b3);

    // Kernel C: PDL-dependent on A.
    {
        cudaLaunchConfig_t cfg = {};
        cfg.gridDim  = dim3(F_, 1, 1);
        cfg.blockDim = dim3(B_, 1, 1);
        cudaLaunchAttribute attr[1];
        attr[0].id = cudaLaunchAttributeProgrammaticStreamSerialization;
        attr[0].val.programmaticStreamSerializationAllowed = 1;
        cfg.attrs = attr;
        cfg.numAttrs = 1;
        cudaLaunchKernelEx(&cfg, fn_node_kernel,
                           s, w1, b1, w2, b2, w3, src1, dst3, g1, bt1, g2, bt2);
    }

    // Kernel D: PDL-dependent on C.
    {
        cudaLaunchConfig_t cfg = {};
        cfg.gridDim  = tgrid;
        cfg.blockDim = tblk;
        cudaLaunchAttribute attr[1];
        attr[0].id = cudaLaunchAttributeProgrammaticStreamSerialization;
        attr[0].val.programmaticStreamSerializationAllowed = 1;
        cfg.attrs = attr;
        cfg.numAttrs = 1;
        cudaLaunchKernelEx(&cfg, transpose_out_kernel, out);
    }
}